// round 11
// baseline (speedup 1.0000x reference)
#include <cuda_runtime.h>
#include <cuda_bf16.h>
#include <cstdint>

#define NJ    32
#define TPB   32                      // single warp per CTA -> warp-sync only
#define BPB   32                      // one batch per thread
#define RECW  292                     // 288 + 4 pad words: 16B-aligned, lane
                                      // stride 292 -> conflict-free LDS.128
#define BUFW  (BPB * RECW)            // 9344 words per buffer
#define SMEM_BYTES (2 * BUFW * 4)     // 74,752 B -> 3 CTAs/SM
#define GRID  444                     // 148 SMs x 3 resident CTAs, persistent

__device__ __forceinline__ void cp_async16(uint32_t s_addr, const void* g_ptr) {
    asm volatile("cp.async.cg.shared.global [%0], [%1], 16;\n"
                 :: "r"(s_addr), "l"(g_ptr));
}

__global__ void __launch_bounds__(TPB)
fk32_kernel(const float* __restrict__ angles,
            const float* __restrict__ offs,
            float* __restrict__ out,
            int batch)
{
    extern __shared__ float s[];          // two BPB-record buffers
    const int t = threadIdx.x;
    const uint32_t sbase = (uint32_t)__cvta_generic_to_shared(s);
    const float4* __restrict__ angv = reinterpret_cast<const float4*>(angles);

    const int par[NJ] = {-1,0,1,2,3,4,0,6,7,8,9,0,11,12,13,14,12,16,17,18,
                         19,20,19,22,12,24,25,26,27,28,27,30};
    const bool isp[NJ] = {1,1,1,1,1,0,1,1,1,1,0,1,1,1,1,0,
                          1,1,1,1,1,0,1,0,1,1,1,1,1,0,1,0};

    const int ntiles = (batch + BPB - 1) / BPB;       // 8192

    // ---- issue one tile's 72 float4/lane into buffer `buf` (dense sweep) ---
    auto issue = [&](int tile2, int buf) {
        const size_t gb = (size_t)tile2 * BPB * 72;
        const uint32_t sb = sbase + (uint32_t)(buf * BUFW) * 4u;
        #pragma unroll
        for (int k = 0; k < 72; ++k) {
            int q   = t + k * TPB;        // 0..2303
            int c   = q / 72;             // record in tile
            int off = q - c * 72;         // float4 within record
            cp_async16(sb + (uint32_t)(c * RECW + off * 4) * 4u,
                       angv + (gb + (size_t)q));
        }
        asm volatile("cp.async.commit_group;\n" ::: "memory");
    };

    // ---- prologue: prefetch first tile into buffer 0
    if (blockIdx.x < ntiles) issue(blockIdx.x, 0);

    int b = 0;
    for (int tile = blockIdx.x; tile < ntiles; tile += GRID) {
        // ---- prefetch next tile into the other buffer (overlaps compute) ---
        const int nxt = tile + GRID;
        const bool have_next = (nxt < ntiles);
        if (have_next) issue(nxt, b ^ 1);

        // ---- wait: current tile landed (next may still be in flight) ------
        if (have_next) asm volatile("cp.async.wait_group 1;" ::: "memory");
        else           asm volatile("cp.async.wait_group 0;" ::: "memory");
        __syncwarp();

        // ===== compute: per-thread full FK from own smem record ============
        {
            float4* recv = reinterpret_cast<float4*>(s + b * BUFW + t * RECW);
            float R[NJ][9];
            float P[NJ][3];

            #pragma unroll
            for (int g = 0; g < 8; ++g) {
                // 9 conflict-free LDS.128: this group's 4 rotation matrices
                float a[36];
                #pragma unroll
                for (int q = 0; q < 9; ++q) {
                    float4 v = recv[g * 9 + q];
                    a[4*q+0] = v.x; a[4*q+1] = v.y; a[4*q+2] = v.z; a[4*q+3] = v.w;
                }

                #pragma unroll
                for (int jj = 0; jj < 4; ++jj) {
                    const int j = g * 4 + jj;
                    const float* Aj = &a[jj * 9];
                    if (j == 0) {
                        #pragma unroll
                        for (int q = 0; q < 9; ++q) R[0][q] = Aj[q];
                        P[0][0] = 0.f; P[0][1] = 0.f; P[0][2] = 0.f;
                    } else {
                        const int p = par[j];
                        const float o0 = __ldg(&offs[j*3+0]);
                        const float o1 = __ldg(&offs[j*3+1]);
                        const float o2 = __ldg(&offs[j*3+2]);
                        #pragma unroll
                        for (int l = 0; l < 3; ++l) {
                            P[j][l] = fmaf(o0, R[p][0*3+l],
                                      fmaf(o1, R[p][1*3+l],
                                      fmaf(o2, R[p][2*3+l], P[p][l])));
                        }
                        if (isp[j]) {
                            #pragma unroll
                            for (int i = 0; i < 3; ++i) {
                                #pragma unroll
                                for (int l = 0; l < 3; ++l) {
                                    R[j][i*3+l] = fmaf(Aj[i*3+0], R[p][0*3+l],
                                                  fmaf(Aj[i*3+1], R[p][1*3+l],
                                                       Aj[i*3+2] * R[p][2*3+l]));
                                }
                            }
                        }
                    }
                }

                // pack positions in place: words [12g,12g+12) belong to input
                // group floor(g/3) <= g, already consumed; in-flight cp.async
                // targets the OTHER buffer, so no async-write conflict.
                const int j0 = g * 4;
                recv[g*3+0] = make_float4(P[j0+0][0], P[j0+0][1], P[j0+0][2], P[j0+1][0]);
                recv[g*3+1] = make_float4(P[j0+1][1], P[j0+1][2], P[j0+2][0], P[j0+2][1]);
                recv[g*3+2] = make_float4(P[j0+2][2], P[j0+3][0], P[j0+3][1], P[j0+3][2]);
            }
        }
        __syncwarp();         // packed positions visible warp-wide

        // ===== flush: coalesced float4 (dense 128B lines) ==================
        {
            float4* dstv = reinterpret_cast<float4*>(out) + (size_t)tile * BPB * 24;
            const float4* sv = reinterpret_cast<const float4*>(s + b * BUFW);
            #pragma unroll
            for (int k = 0; k < 24; ++k) {
                int q   = t + k * TPB;        // 0..767
                int c   = q / 24;
                int off = q - c * 24;
                if ((size_t)tile * BPB + (size_t)c < (size_t)batch)
                    dstv[q] = sv[c * (RECW / 4) + off];
            }
        }
        __syncwarp();         // flush LDS issued before this buffer is refilled
        b ^= 1;
    }
}

extern "C" void kernel_launch(void* const* d_in, const int* in_sizes, int n_in,
                              void* d_out, int out_size)
{
    const float* angles = (const float*)d_in[0];
    const float* offs   = (const float*)d_in[1];
    float* out          = (float*)d_out;

    int batch = in_sizes[0] / (NJ * 9);               // 262144

    static bool attr_done = false;
    if (!attr_done) {
        cudaFuncSetAttribute(fk32_kernel,
                             cudaFuncAttributeMaxDynamicSharedMemorySize,
                             SMEM_BYTES);
        attr_done = true;
    }

    fk32_kernel<<<GRID, TPB, SMEM_BYTES>>>(angles, offs, out, batch);
}

// round 15
// speedup vs baseline: 1.1683x; 1.1683x over previous
#include <cuda_runtime.h>
#include <cuda_bf16.h>
#include <cstdint>

#define NJ     32
#define TPB    32                    // single warp per CTA -> __syncwarp only
#define BPB    32                    // one batch per thread
#define NS     3                     // cp.async ring depth (group-granular)
#define INROW  36                    // words/record/group: stride 36 = 4 mod 32
                                     //  -> 16B-aligned + conflict-free LDS.128
#define STAGEW (BPB * INROW)         // 1152 words = 4608 B per stage
#define OUTROW 100                   // 96 pos words + 4 pad (100 = 4 mod 32)
#define OUTW   (BPB * OUTROW)        // 3200 words
#define SMEM_WORDS (NS * STAGEW + OUTW)      // 6656 words
#define SMEM_BYTES (SMEM_WORDS * 4)          // 26,624 B -> 8 CTAs/SM
#define GRID   1184                  // 148 SMs x 8 resident CTAs, persistent

__device__ __forceinline__ void cp_async16(uint32_t s_addr, const void* g_ptr) {
    asm volatile("cp.async.cg.shared.global [%0], [%1], 16;\n"
                 :: "r"(s_addr), "l"(g_ptr));
}

__global__ void __launch_bounds__(TPB)
fk32_kernel(const float* __restrict__ angles,
            const float* __restrict__ offs,
            float* __restrict__ out,
            int batch)
{
    extern __shared__ float s[];
    const int t   = threadIdx.x;
    const int bid = blockIdx.x;
    const uint32_t sbase = (uint32_t)__cvta_generic_to_shared(s);
    const float4* __restrict__ angv = reinterpret_cast<const float4*>(angles);
    float4* outv = reinterpret_cast<float4*>(s + NS * STAGEW);

    const int ntiles = (batch + BPB - 1) / BPB;       // 8192
    if (bid >= ntiles) return;

    const int par[NJ] = {-1,0,1,2,3,4,0,6,7,8,9,0,11,12,13,14,12,16,17,18,
                         19,20,19,22,12,24,25,26,27,28,27,30};
    const bool isp[NJ] = {1,1,1,1,1,0,1,1,1,1,0,1,1,1,1,0,
                          1,1,1,1,1,0,1,0,1,1,1,1,1,0,1,0};

    const int nmine = (ntiles - bid + GRID - 1) / GRID;
    const int M     = nmine * 8;      // my chunk count; chunk m = (tile, group)

    // ---- chunk issuer: one group-slice of one tile -> stage m%NS -----------
    auto issue = [&](int mm) {
        const int tile2 = bid + (mm >> 3) * GRID;
        const int g2    = mm & 7;
        const int cmax  = min(BPB, batch - tile2 * BPB) - 1;
        const size_t gb = (size_t)tile2 * BPB * 72 + (size_t)g2 * 9;
        const uint32_t sb = sbase + (uint32_t)((mm % NS) * STAGEW) * 4u;
        #pragma unroll
        for (int i = 0; i < 9; ++i) {
            int e  = t + i * TPB;         // 0..287
            int c  = e / 9;               // record in tile
            int ip = e - c * 9;           // float4 within 144B slice
            int cc = min(c, cmax);
            cp_async16(sb + (uint32_t)(cc * INROW + ip * 4) * 4u,
                       angv + (gb + (size_t)cc * 72 + ip));
        }
        asm volatile("cp.async.commit_group;\n" ::: "memory");
    };

    // ---- prologue: fill the ring (NS-1 younger kept pending in steady state)
    #pragma unroll
    for (int mm = 0; mm < NS; ++mm)
        if (mm < M) issue(mm);

    float R[NJ][9];
    float P[NJ][3];

    int m = 0;
    for (int tile = bid; tile < ntiles; tile += GRID) {
        #pragma unroll
        for (int g = 0; g < 8; ++g) {
            // ---- wait: chunk m landed (pending younger: <= NS-1) ----------
            if (m + 3 <= M)      asm volatile("cp.async.wait_group 2;" ::: "memory");
            else if (m + 2 == M) asm volatile("cp.async.wait_group 1;" ::: "memory");
            else                 asm volatile("cp.async.wait_group 0;" ::: "memory");
            __syncwarp();         // publish stage across lanes (writers != readers)

            // ---- consume: 9 conflict-free LDS.128 from stage m%NS ---------
            const float4* stv =
                reinterpret_cast<const float4*>(s + (m % NS) * STAGEW) + t * 9;
            float a[36];
            #pragma unroll
            for (int q = 0; q < 9; ++q) {
                float4 v = stv[q];
                a[4*q+0] = v.x; a[4*q+1] = v.y; a[4*q+2] = v.z; a[4*q+3] = v.w;
            }

            // ---- FK for joints 4g..4g+3 (compile-time indices) ------------
            #pragma unroll
            for (int jj = 0; jj < 4; ++jj) {
                const int j = g * 4 + jj;
                const float* Aj = &a[jj * 9];
                if (j == 0) {
                    #pragma unroll
                    for (int q = 0; q < 9; ++q) R[0][q] = Aj[q];
                    P[0][0] = 0.f; P[0][1] = 0.f; P[0][2] = 0.f;
                } else {
                    const int p = par[j];
                    const float o0 = __ldg(&offs[j*3+0]);
                    const float o1 = __ldg(&offs[j*3+1]);
                    const float o2 = __ldg(&offs[j*3+2]);
                    #pragma unroll
                    for (int l = 0; l < 3; ++l) {
                        P[j][l] = fmaf(o0, R[p][0*3+l],
                                  fmaf(o1, R[p][1*3+l],
                                  fmaf(o2, R[p][2*3+l], P[p][l])));
                    }
                    if (isp[j]) {
                        #pragma unroll
                        for (int i = 0; i < 3; ++i) {
                            #pragma unroll
                            for (int l = 0; l < 3; ++l) {
                                R[j][i*3+l] = fmaf(Aj[i*3+0], R[p][0*3+l],
                                              fmaf(Aj[i*3+1], R[p][1*3+l],
                                                   Aj[i*3+2] * R[p][2*3+l]));
                            }
                        }
                    }
                }
            }

            // ---- stage positions: 3 conflict-free STS.128 -----------------
            {
                const int j0 = g * 4;
                float4* orow = outv + t * (OUTROW / 4);
                orow[g*3+0] = make_float4(P[j0+0][0], P[j0+0][1], P[j0+0][2], P[j0+1][0]);
                orow[g*3+1] = make_float4(P[j0+1][1], P[j0+1][2], P[j0+2][0], P[j0+2][1]);
                orow[g*3+2] = make_float4(P[j0+2][2], P[j0+3][0], P[j0+3][1], P[j0+3][2]);
            }

            // ---- refill: reuse the stage just consumed --------------------
            if (m + NS < M) issue(m + NS);
            ++m;

            // ---- tile complete: coalesced float4 flush --------------------
            if (g == 7) {
                __syncwarp();     // all lanes' STS to out tile visible
                float4* dstv = reinterpret_cast<float4*>(out) + (size_t)tile * BPB * 24;
                #pragma unroll
                for (int k = 0; k < 24; ++k) {
                    int q   = t + k * TPB;        // 0..767
                    int c   = q / 24;
                    int off = q - c * 24;
                    if ((size_t)tile * BPB + (size_t)c < (size_t)batch)
                        dstv[q] = outv[c * (OUTROW / 4) + off];
                }
                // per-warp program order fences these LDS before the next
                // tile's STS to the out tile.
            }
        }
    }
}

extern "C" void kernel_launch(void* const* d_in, const int* in_sizes, int n_in,
                              void* d_out, int out_size)
{
    const float* angles = (const float*)d_in[0];
    const float* offs   = (const float*)d_in[1];
    float* out          = (float*)d_out;

    int batch = in_sizes[0] / (NJ * 9);               // 262144

    static bool attr_done = false;
    if (!attr_done) {
        cudaFuncSetAttribute(fk32_kernel,
                             cudaFuncAttributeMaxDynamicSharedMemorySize,
                             SMEM_BYTES);
        attr_done = true;
    }

    fk32_kernel<<<GRID, TPB, SMEM_BYTES>>>(angles, offs, out, batch);
}

// round 16
// speedup vs baseline: 1.2618x; 1.0801x over previous
#include <cuda_runtime.h>
#include <cuda_bf16.h>
#include <cstdint>

#define NJ     32
#define TPB    32                    // single warp per CTA
#define BPB    32                    // one batch (record) per lane
#define RECW   292                   // 288 + 4 pad words; addr16 stride 73 = 1 mod 8
                                     //  -> conflict-free LDS.128
#define OUTROW 100                   // 96 + 4 pad words; addr16 stride 25 = 1 mod 8
#define IN_WORDS  (BPB * RECW)       // 9344
#define OUT_BASE  IN_WORDS
#define OUT_WORDS (BPB * OUTROW)     // 3200
#define MBAR_WORD (OUT_BASE + OUT_WORDS)        // 12544
#define SMEM_BYTES (MBAR_WORD * 4 + 16)         // 50,192 B -> 4 CTAs/SM
#define GRID   592                   // 148 SMs x 4 resident CTAs, persistent

#define HALF_BYTES 576u              // 36 float4 = groups 0-3 (or 4-7)

// ---------------- async-engine primitives (1D bulk, no tensor map) ----------
__device__ __forceinline__ void mbar_init(uint32_t mb, uint32_t cnt) {
    asm volatile("mbarrier.init.shared::cta.b64 [%0], %1;" :: "r"(mb), "r"(cnt));
}
__device__ __forceinline__ void mbar_expect(uint32_t mb, uint32_t bytes) {
    asm volatile("mbarrier.arrive.expect_tx.shared::cta.b64 _, [%0], %1;"
                 :: "r"(mb), "r"(bytes) : "memory");
}
__device__ __forceinline__ void bulk_ld(uint32_t sdst, const void* gsrc,
                                        uint32_t bytes, uint32_t mb) {
    asm volatile("cp.async.bulk.shared::cta.global.mbarrier::complete_tx::bytes "
                 "[%0], [%1], %2, [%3];"
                 :: "r"(sdst), "l"(gsrc), "r"(bytes), "r"(mb) : "memory");
}
__device__ __forceinline__ void bulk_st(void* gdst, uint32_t ssrc, uint32_t bytes) {
    asm volatile("cp.async.bulk.global.shared::cta.bulk_group [%0], [%1], %2;"
                 :: "l"(gdst), "r"(ssrc), "r"(bytes) : "memory");
}
__device__ __forceinline__ void bulk_st_commit() {
    asm volatile("cp.async.bulk.commit_group;" ::: "memory");
}
__device__ __forceinline__ void bulk_st_wait_read0() {
    asm volatile("cp.async.bulk.wait_group.read 0;" ::: "memory");
}
__device__ __forceinline__ void fence_async() {
    asm volatile("fence.proxy.async.shared::cta;" ::: "memory");
}
__device__ __forceinline__ void mwait(uint32_t mb, uint32_t phase) {
    uint32_t done;
    asm volatile("{\n\t.reg .pred p;\n\t"
                 "mbarrier.try_wait.parity.acquire.cta.shared::cta.b64 p, [%1], %2;\n\t"
                 "selp.b32 %0, 1, 0, p;\n\t}"
                 : "=r"(done) : "r"(mb), "r"(phase) : "memory");
    if (!done) {
        asm volatile("{\n\t.reg .pred P1;\n\t"
                     "W%=:\n\t"
                     "mbarrier.try_wait.parity.acquire.cta.shared::cta.b64 P1, [%0], %1, 0x989680;\n\t"
                     "@P1 bra.uni D%=;\n\t"
                     "bra.uni W%=;\n\t"
                     "D%=:\n\t}"
                     :: "r"(mb), "r"(phase) : "memory");
    }
}

__global__ void __launch_bounds__(TPB)
fk32_kernel(const float* __restrict__ angles,
            const float* __restrict__ offs,
            float* __restrict__ out,
            int batch)
{
    extern __shared__ float s[];
    const int t   = threadIdx.x;
    const int bid = blockIdx.x;
    const uint32_t sbase = (uint32_t)__cvta_generic_to_shared(s);

    const uint32_t mbA = sbase + (uint32_t)MBAR_WORD * 4u;
    const uint32_t mbB = mbA + 8u;
    const uint32_t inrow = sbase + (uint32_t)(t * RECW) * 4u;      // lane's record row
    const uint32_t orow  = sbase + (uint32_t)(OUT_BASE + t * OUTROW) * 4u;

    const int ntiles = (batch + BPB - 1) / BPB;        // 8192
    if (bid >= ntiles) return;

    if (t == 0) { mbar_init(mbA, TPB); mbar_init(mbB, TPB); }
    __syncwarp();
    fence_async();          // publish barrier init to the async proxy

    const int par[NJ] = {-1,0,1,2,3,4,0,6,7,8,9,0,11,12,13,14,12,16,17,18,
                         19,20,19,22,12,24,25,26,27,28,27,30};
    const bool isp[NJ] = {1,1,1,1,1,0,1,1,1,1,0,1,1,1,1,0,
                          1,1,1,1,1,0,1,0,1,1,1,1,1,0,1,0};

    // lane's record byte address for tile `tl`
    auto grec = [&](int tl) -> const char* {
        long r = (long)tl * BPB + t;
        if (r >= batch) r = batch - 1;          // safe clamp (exact tiles here)
        return reinterpret_cast<const char*>(angles) + (size_t)r * 1152u;
    };

    // ---- prologue: both halves of first tile in flight ---------------------
    mbar_expect(mbA, HALF_BYTES);
    bulk_ld(inrow, grec(bid), HALF_BYTES, mbA);
    mbar_expect(mbB, HALF_BYTES);
    bulk_ld(inrow + HALF_BYTES, grec(bid) + HALF_BYTES, HALF_BYTES, mbB);

    float R[NJ][9];
    float P[NJ][3];
    const float4* recv = reinterpret_cast<const float4*>(s + t * RECW);
    float4*       ov   = reinterpret_cast<float4*>(s + OUT_BASE + t * OUTROW);

    uint32_t pa = 0, pb = 0;

    for (int tile = bid; tile < ntiles; tile += GRID) {
        const int  nxt  = tile + GRID;
        const bool more = (nxt < ntiles);

        // ================= half A: groups 0..3 =============================
        mwait(mbA, pa); pa ^= 1;          // bytes [0,576) of my record landed
        bulk_st_wait_read0();             // my out row free (prev tile's store read)

        #pragma unroll
        for (int g = 0; g < 4; ++g) {
            float a[36];
            #pragma unroll
            for (int q = 0; q < 9; ++q) {
                float4 v = recv[g * 9 + q];
                a[4*q+0] = v.x; a[4*q+1] = v.y; a[4*q+2] = v.z; a[4*q+3] = v.w;
            }
            #pragma unroll
            for (int jj = 0; jj < 4; ++jj) {
                const int j = g * 4 + jj;
                const float* Aj = &a[jj * 9];
                if (j == 0) {
                    #pragma unroll
                    for (int q = 0; q < 9; ++q) R[0][q] = Aj[q];
                    P[0][0] = 0.f; P[0][1] = 0.f; P[0][2] = 0.f;
                } else {
                    const int p = par[j];
                    const float o0 = __ldg(&offs[j*3+0]);
                    const float o1 = __ldg(&offs[j*3+1]);
                    const float o2 = __ldg(&offs[j*3+2]);
                    #pragma unroll
                    for (int l = 0; l < 3; ++l) {
                        P[j][l] = fmaf(o0, R[p][0*3+l],
                                  fmaf(o1, R[p][1*3+l],
                                  fmaf(o2, R[p][2*3+l], P[p][l])));
                    }
                    if (isp[j]) {
                        #pragma unroll
                        for (int i = 0; i < 3; ++i) {
                            #pragma unroll
                            for (int l = 0; l < 3; ++l) {
                                R[j][i*3+l] = fmaf(Aj[i*3+0], R[p][0*3+l],
                                              fmaf(Aj[i*3+1], R[p][1*3+l],
                                                   Aj[i*3+2] * R[p][2*3+l]));
                            }
                        }
                    }
                }
            }
            const int j0 = g * 4;
            ov[g*3+0] = make_float4(P[j0+0][0], P[j0+0][1], P[j0+0][2], P[j0+1][0]);
            ov[g*3+1] = make_float4(P[j0+1][1], P[j0+1][2], P[j0+2][0], P[j0+2][1]);
            ov[g*3+2] = make_float4(P[j0+2][2], P[j0+3][0], P[j0+3][1], P[j0+3][2]);
        }

        // half A consumed -> stream next tile's half A immediately
        if (more) {
            mbar_expect(mbA, HALF_BYTES);
            bulk_ld(inrow, grec(nxt), HALF_BYTES, mbA);
        }

        // ================= half B: groups 4..7 =============================
        mwait(mbB, pb); pb ^= 1;

        #pragma unroll
        for (int g = 4; g < 8; ++g) {
            float a[36];
            #pragma unroll
            for (int q = 0; q < 9; ++q) {
                float4 v = recv[g * 9 + q];
                a[4*q+0] = v.x; a[4*q+1] = v.y; a[4*q+2] = v.z; a[4*q+3] = v.w;
            }
            #pragma unroll
            for (int jj = 0; jj < 4; ++jj) {
                const int j = g * 4 + jj;
                const float* Aj = &a[jj * 9];
                {
                    const int p = par[j];
                    const float o0 = __ldg(&offs[j*3+0]);
                    const float o1 = __ldg(&offs[j*3+1]);
                    const float o2 = __ldg(&offs[j*3+2]);
                    #pragma unroll
                    for (int l = 0; l < 3; ++l) {
                        P[j][l] = fmaf(o0, R[p][0*3+l],
                                  fmaf(o1, R[p][1*3+l],
                                  fmaf(o2, R[p][2*3+l], P[p][l])));
                    }
                    if (isp[j]) {
                        #pragma unroll
                        for (int i = 0; i < 3; ++i) {
                            #pragma unroll
                            for (int l = 0; l < 3; ++l) {
                                R[j][i*3+l] = fmaf(Aj[i*3+0], R[p][0*3+l],
                                              fmaf(Aj[i*3+1], R[p][1*3+l],
                                                   Aj[i*3+2] * R[p][2*3+l]));
                            }
                        }
                    }
                }
            }
            const int j0 = g * 4;
            ov[g*3+0] = make_float4(P[j0+0][0], P[j0+0][1], P[j0+0][2], P[j0+1][0]);
            ov[g*3+1] = make_float4(P[j0+1][1], P[j0+1][2], P[j0+2][0], P[j0+2][1]);
            ov[g*3+2] = make_float4(P[j0+2][2], P[j0+3][0], P[j0+3][1], P[j0+3][2]);
        }

        if (more) {
            mbar_expect(mbB, HALF_BYTES);
            bulk_ld(inrow + HALF_BYTES, grec(nxt) + HALF_BYTES, HALF_BYTES, mbB);
        }

        // ================= store: one 384B bulk per lane ===================
        fence_async();                    // order my STS before async-proxy read
        {
            long r = (long)tile * BPB + t;
            if (r < batch)
                bulk_st(out + (size_t)r * 96u, orow, 384u);
            bulk_st_commit();             // every lane commits (possibly empty group)
        }
    }
    bulk_st_wait_read0();                 // drain before exit
}

extern "C" void kernel_launch(void* const* d_in, const int* in_sizes, int n_in,
                              void* d_out, int out_size)
{
    const float* angles = (const float*)d_in[0];
    const float* offs   = (const float*)d_in[1];
    float* out          = (float*)d_out;

    int batch = in_sizes[0] / (NJ * 9);                // 262144

    static bool attr_done = false;
    if (!attr_done) {
        cudaFuncSetAttribute(fk32_kernel,
                             cudaFuncAttributeMaxDynamicSharedMemorySize,
                             SMEM_BYTES);
        attr_done = true;
    }

    fk32_kernel<<<GRID, TPB, SMEM_BYTES>>>(angles, offs, out, batch);
}